// round 16
// baseline (speedup 1.0000x reference)
#include <cuda_runtime.h>
#include <cstdint>
#include <math.h>

#define B_IMG 8
#define NPROP 4000
#define NCLS 91
#define NCM1 90
#define CAPC 4000                    // worst-case candidates per (image,class)
#define NDET 100
#define NEGV -1e9f
#define CAPSM 512                    // smem sort cap for class NMS
#define MASKN 320                    // mask-path cap
#define MW 10                        // u32 mask words per row (MASKN/32)
#define SV_PER_IMG (NCM1 * NDET)     // 9000 survivors per image (capped)
#define GCAP 1024                    // topk rank-sort capacity
#define NBLKA 2000                   // phaseAB blocks (16 proposals each)
#define QCAP 320                     // smem queue cap (<=20 passers/proposal)
#define FULLM 0xffffffffu

static __device__ float4        g_cbox[B_IMG * NCM1 * CAPC];
static __device__ float         g_cs[B_IMG * NCM1 * CAPC];
static __device__ int           g_ccnt[B_IMG * NCM1];    // zero-init, self-reset
static __device__ float4        g_svbox[B_IMG * SV_PER_IMG];
static __device__ float         g_svsc[B_IMG * SV_PER_IMG];
static __device__ unsigned char g_svlab[B_IMG * SV_PER_IMG];
static __device__ int           g_svcnt[B_IMG];          // zero-init, self-reset
static __device__ float         g_T[B_IMG];              // overwritten each replay

__device__ __forceinline__ float load_dim(const int* p) {
    int vi = *p;
    if (vi > 0 && vi < 1000000) return (float)vi;
    return __int_as_float(vi);
}

// ---------------------------------------------------------------------------
// Phase AB (fused): softmax + threshold filter -> smem queue -> dense decode.
// (at MUFU floor ~20us; unchanged)
// ---------------------------------------------------------------------------
__global__ void __launch_bounds__(256)
phaseAB_kernel(const float* __restrict__ logits,
               const float* __restrict__ reg,
               const float* __restrict__ props,
               const int* __restrict__ ph,
               const int* __restrict__ pw) {
    const int warp = threadIdx.x >> 5;
    const int lane = threadIdx.x & 31;
    const int p0 = (blockIdx.x * 8 + warp) << 1;

    __shared__ unsigned long long q[QCAP];
    __shared__ int s_cnt;
    if (threadIdx.x == 0) s_cnt = 0;
    __syncthreads();

    const float* z0 = logits + (size_t)p0 * NCLS;
    const float* z1 = z0 + NCLS;

    float e[2][3];
    e[0][0] = __expf(z0[lane]);
    e[1][0] = __expf(z1[lane]);
    e[0][1] = __expf(z0[lane + 32]);
    e[1][1] = __expf(z1[lane + 32]);
    e[0][2] = (lane < NCLS - 64) ? __expf(z0[lane + 64]) : 0.0f;
    e[1][2] = (lane < NCLS - 64) ? __expf(z1[lane + 64]) : 0.0f;

    float ssum[2];
    ssum[0] = e[0][0] + e[0][1] + e[0][2];
    ssum[1] = e[1][0] + e[1][1] + e[1][2];
    #pragma unroll
    for (int o = 16; o; o >>= 1) {
        ssum[0] += __shfl_xor_sync(FULLM, ssum[0], o);
        ssum[1] += __shfl_xor_sync(FULLM, ssum[1], o);
    }

    bool pass[6];
    int cnt = 0;
    #pragma unroll
    for (int k = 0; k < 2; k++) {
        float thr = 0.05f * ssum[k];
        #pragma unroll
        for (int t = 0; t < 3; t++) {
            int c = lane + 32 * t;
            bool pk = (c > 0) && (c < NCLS) && (e[k][t] > thr);
            pass[k * 3 + t] = pk;
            cnt += pk ? 1 : 0;
        }
    }

    int incl = cnt;
    #pragma unroll
    for (int o = 1; o < 32; o <<= 1) {
        int v = __shfl_up_sync(FULLM, incl, o);
        if (lane >= o) incl += v;
    }
    int total = __shfl_sync(FULLM, incl, 31);
    int wbase = 0;
    if (total > 0) {
        if (lane == 31) wbase = atomicAdd(&s_cnt, total);
        wbase = __shfl_sync(FULLM, wbase, 31);
        int off = wbase + incl - cnt;
        #pragma unroll
        for (int k = 0; k < 2; k++) {
            #pragma unroll
            for (int t = 0; t < 3; t++) {
                if (pass[k * 3 + t]) {
                    int c = lane + 32 * t;
                    float sc = e[k][t] / ssum[k];
                    unsigned idx = ((unsigned)(p0 + k) << 7) | (unsigned)c;
                    q[off++] = ((unsigned long long)__float_as_uint(sc) << 32) | idx;
                }
            }
        }
    }
    __syncthreads();

    const int qcnt = s_cnt;
    const float Wf = load_dim(pw);
    const float Hf = load_dim(ph);
    const float CLIPV = 4.135166556742356f;  // log(1000/16)

    for (int i = threadIdx.x; i < qcnt; i += 256) {
        unsigned long long en = q[i];
        float sc = __uint_as_float((unsigned)(en >> 32));
        unsigned idx = (unsigned)en;
        int p = idx >> 7, c = idx & 127;

        float4 pr = ((const float4*)props)[p];
        float w = pr.z - pr.x, h = pr.w - pr.y;
        float cx = pr.x + 0.5f * w, cy = pr.y + 0.5f * h;
        float4 r = ((const float4*)reg)[p * NCLS + c];

        float dx = r.x / 10.0f, dy = r.y / 10.0f;
        float dw = fminf(r.z / 5.0f, CLIPV);
        float dh = fminf(r.w / 5.0f, CLIPV);
        float pcx = dx * w + cx, pcy = dy * h + cy;
        float pwd = __expf(dw) * w, phd = __expf(dh) * h;
        float x1 = pcx - 0.5f * pwd, y1 = pcy - 0.5f * phd;
        float x2 = pcx + 0.5f * pwd, y2 = pcy + 0.5f * phd;
        x1 = fminf(fmaxf(x1, 0.0f), Wf); x2 = fminf(fmaxf(x2, 0.0f), Wf);
        y1 = fminf(fmaxf(y1, 0.0f), Hf); y2 = fminf(fmaxf(y2, 0.0f), Hf);
        if ((x2 - x1) >= 0.01f && (y2 - y1) >= 0.01f) {
            int b = p / NPROP;
            int bc = b * NCM1 + (c - 1);
            int pos = atomicAdd(&g_ccnt[bc], 1);
            size_t o = (size_t)bc * CAPC + pos;
            g_cbox[o] = make_float4(x1, y1, x2, y2);
            g_cs[o]   = sc;
        }
    }
}

// ---------------------------------------------------------------------------
// Threshold kernel: one block per image. Per class: top survivor score and
// best non-overlapping (2nd survivor) score — both provably greedy survivors.
// T = 100th largest of these; candidates with score < T are provably
// irrelevant to the final output.
// ---------------------------------------------------------------------------
__global__ void __launch_bounds__(1024)
thresh_kernel(void) {
    const int b = blockIdx.x;
    const int tid = threadIdx.x;
    const int wid = tid >> 5;
    const int lane = tid & 31;

    __shared__ unsigned long long vals[192];
    __shared__ float T_s;
    for (int i = tid; i < 192; i += 1024) vals[i] = 0ull;
    if (tid == 0) T_s = 0.0f;
    __syncthreads();

    for (int t = wid; t < NCM1; t += 32) {
        const int bc = b * NCM1 + t;
        const int n = g_ccnt[bc];
        if (n == 0) continue;               // n uniform across warp
        const size_t base = (size_t)bc * CAPC;

        float m1 = -2e9f; int i1 = 0x7fffffff;
        for (int j = lane; j < n; j += 32) {
            float s = g_cs[base + j];
            if (s > m1) { m1 = s; i1 = j; }
        }
        #pragma unroll
        for (int o = 16; o; o >>= 1) {
            float ov = __shfl_xor_sync(FULLM, m1, o);
            int   oi = __shfl_xor_sync(FULLM, i1, o);
            if (ov > m1 || (ov == m1 && oi < i1)) { m1 = ov; i1 = oi; }
        }

        float4 b1 = g_cbox[base + i1];
        float a1 = (b1.z - b1.x) * (b1.w - b1.y);
        float m2 = -2e9f;
        for (int j = lane; j < n; j += 32) {
            if (j == i1) continue;
            float s = g_cs[base + j];
            if (s <= m2) continue;
            float4 bj = g_cbox[base + j];
            float ix1 = fmaxf(b1.x, bj.x), iy1 = fmaxf(b1.y, bj.y);
            float ix2 = fminf(b1.z, bj.z), iy2 = fminf(b1.w, bj.w);
            float inter = fmaxf(ix2 - ix1, 0.0f) * fmaxf(iy2 - iy1, 0.0f);
            float aj = (bj.z - bj.x) * (bj.w - bj.y);
            if (!(inter > 0.5f * (a1 + aj - inter))) m2 = s;   // survives round 1
        }
        #pragma unroll
        for (int o = 16; o; o >>= 1)
            m2 = fmaxf(m2, __shfl_xor_sync(FULLM, m2, o));

        if (lane == 0) {
            vals[2 * t] = ((unsigned long long)__float_as_uint(m1) << 32)
                        | (unsigned)(2 * t);
            if (m2 > 0.0f)
                vals[2 * t + 1] = ((unsigned long long)__float_as_uint(m2) << 32)
                                | (unsigned)(2 * t + 1);
        }
    }
    __syncthreads();

    if (tid < 192) {
        unsigned long long ki = vals[tid];
        if (ki != 0ull) {
            int r = 0;
            for (int j = 0; j < 192; j++) r += (vals[j] > ki);
            if (r == 99) T_s = __uint_as_float((unsigned)(ki >> 32));
        }
    }
    __syncthreads();
    if (tid == 0) g_T[b] = T_s;
}

// ---------------------------------------------------------------------------
// Phase B: one block per (image,class). Prune to score >= T[b] (exact), then
// x4-row ballot rank sort + x4-row ballot mask build + warp-0 register greedy
// scan. Survivors to per-image global list (no histogram).
// ---------------------------------------------------------------------------
__global__ void __launch_bounds__(256, 5)
class_nms_kernel(const int* __restrict__ ph, const int* __restrict__ pw) {
    const int c  = blockIdx.x + 1;
    const int b  = blockIdx.y;
    const int bc = b * NCM1 + (c - 1);
    const int tid = threadIdx.x;
    const int wid = tid >> 5;
    const int lane = tid & 31;
    const int n = g_ccnt[bc];
    if (n == 0) return;

    __shared__ unsigned long long skey[CAPSM];
    __shared__ unsigned long long ssort[CAPSM];
    __shared__ float4             sbox[CAPSM];
    __shared__ float              sarea[CAPSM];
    __shared__ unsigned int       mrow[MASKN * MW];
    __shared__ unsigned char      alive[CAPSM];
    __shared__ unsigned short     surv[NDET];
    __shared__ int                nsurv_s, sbase_s, cn_s;
    __shared__ float              red_v[8];
    __shared__ int                red_i[8];
    __shared__ int                stop_s, seli_s;
    __shared__ float4             selbox_s;
    __shared__ float              gsc_s;

    const size_t base = (size_t)bc * CAPC;

    if (n <= CAPSM) {
        // ---- prune + compact (score >= T is exact; see thresh_kernel) ----
        const float T = g_T[b];
        if (tid == 0) cn_s = 0;
        __syncthreads();
        for (int j = tid; j < n; j += 256) {
            float s = g_cs[base + j];
            if (s >= T) {
                int p = atomicAdd(&cn_s, 1);
                skey[p] = ((unsigned long long)__float_as_uint(s) << 32)
                        | (unsigned)j;
            }
        }
        __syncthreads();
        const int n2 = cn_s;

        if (n2 > 0) {
        const int NW32 = (n2 + 31) >> 5;
        const int im = n2 - 1;

        // x4-row ballot rank sort
        for (int i0 = wid << 2; i0 < n2; i0 += 32) {
            unsigned long long k0 = skey[i0];
            unsigned long long k1 = skey[min(i0 + 1, im)];
            unsigned long long k2 = skey[min(i0 + 2, im)];
            unsigned long long k3 = skey[min(i0 + 3, im)];
            int r0 = 0, r1 = 0, r2 = 0, r3 = 0;
            for (int jb = 0; jb < NW32; jb++) {
                int j = (jb << 5) + lane;
                bool v = j < n2;
                unsigned long long kj = skey[v ? j : 0];
                r0 += __popc(__ballot_sync(FULLM, v && (kj > k0)));
                r1 += __popc(__ballot_sync(FULLM, v && (kj > k1)));
                r2 += __popc(__ballot_sync(FULLM, v && (kj > k2)));
                r3 += __popc(__ballot_sync(FULLM, v && (kj > k3)));
            }
            if (lane < 4 && i0 + lane < n2) {
                int rr = (lane == 0) ? r0 : (lane == 1) ? r1 : (lane == 2) ? r2 : r3;
                unsigned long long kk =
                    (lane == 0) ? k0 : (lane == 1) ? k1 : (lane == 2) ? k2 : k3;
                ssort[rr] = kk;
            }
        }
        __syncthreads();

        for (int i = tid; i < n2; i += 256) {
            float4 bx = g_cbox[base + (unsigned)(ssort[i] & 0xffffffffu)];
            sbox[i]  = bx;
            sarea[i] = (bx.z - bx.x) * (bx.w - bx.y);
        }
        __syncthreads();

        if (n2 <= MASKN) {
            // ---- x4-row ballot mask build ----
            for (int i0 = wid << 2; i0 < n2; i0 += 32) {
                float4 b0 = sbox[i0];
                float4 b1 = sbox[min(i0 + 1, im)];
                float4 b2 = sbox[min(i0 + 2, im)];
                float4 b3 = sbox[min(i0 + 3, im)];
                float a0 = sarea[i0];
                float a1 = sarea[min(i0 + 1, im)];
                float a2 = sarea[min(i0 + 2, im)];
                float a3 = sarea[min(i0 + 3, im)];
                for (int jb = i0 >> 5; jb < NW32; jb++) {
                    int j = (jb << 5) + lane;
                    bool v = j < n2;
                    float4 bj = sbox[v ? j : 0];
                    float aj  = sarea[v ? j : 0];
                    int jgt = j - i0;
                    float ix1, iy1, ix2, iy2, inter;
                    ix1 = fmaxf(b0.x, bj.x); iy1 = fmaxf(b0.y, bj.y);
                    ix2 = fminf(b0.z, bj.z); iy2 = fminf(b0.w, bj.w);
                    inter = fmaxf(ix2 - ix1, 0.0f) * fmaxf(iy2 - iy1, 0.0f);
                    unsigned m0 = __ballot_sync(FULLM,
                        v && (jgt > 0) && (inter > 0.5f * (a0 + aj - inter)));
                    ix1 = fmaxf(b1.x, bj.x); iy1 = fmaxf(b1.y, bj.y);
                    ix2 = fminf(b1.z, bj.z); iy2 = fminf(b1.w, bj.w);
                    inter = fmaxf(ix2 - ix1, 0.0f) * fmaxf(iy2 - iy1, 0.0f);
                    unsigned m1 = __ballot_sync(FULLM,
                        v && (jgt > 1) && (inter > 0.5f * (a1 + aj - inter)));
                    ix1 = fmaxf(b2.x, bj.x); iy1 = fmaxf(b2.y, bj.y);
                    ix2 = fminf(b2.z, bj.z); iy2 = fminf(b2.w, bj.w);
                    inter = fmaxf(ix2 - ix1, 0.0f) * fmaxf(iy2 - iy1, 0.0f);
                    unsigned m2 = __ballot_sync(FULLM,
                        v && (jgt > 2) && (inter > 0.5f * (a2 + aj - inter)));
                    ix1 = fmaxf(b3.x, bj.x); iy1 = fmaxf(b3.y, bj.y);
                    ix2 = fminf(b3.z, bj.z); iy2 = fminf(b3.w, bj.w);
                    inter = fmaxf(ix2 - ix1, 0.0f) * fmaxf(iy2 - iy1, 0.0f);
                    unsigned m3 = __ballot_sync(FULLM,
                        v && (jgt > 3) && (inter > 0.5f * (a3 + aj - inter)));
                    if (lane < 4 && i0 + lane < n2) {
                        unsigned mv =
                            (lane == 0) ? m0 : (lane == 1) ? m1 : (lane == 2) ? m2 : m3;
                        mrow[(i0 + lane) * MW + jb] = mv;
                    }
                }
            }
            __syncthreads();

            // ---- greedy scan, warp 0, dead-words in registers ----
            if (wid == 0) {
                unsigned dead = 0;    // lane L owns dead word L
                int ns = 0;
                for (int i = 0; i < n2 && ns < NDET; i++) {
                    unsigned dw = __shfl_sync(FULLM, dead, i >> 5);
                    if (!((dw >> (i & 31)) & 1u)) {
                        if (lane == 0) surv[ns] = (unsigned short)i;
                        ns++;
                        if (lane < NW32 && lane >= (i >> 5))
                            dead |= mrow[i * MW + lane];
                    }
                }
                if (lane == 0) {
                    nsurv_s = ns;
                    sbase_s = atomicAdd(&g_svcnt[b], ns);
                }
            }
        } else {
            // ---- maskless warp-greedy mid path (MASKN < n2 <= CAPSM) ----
            for (int i = tid; i < n2; i += 256) alive[i] = 1;
            __syncthreads();
            if (wid == 0) {
                int ns = 0;
                for (int i = 0; i < n2 && ns < NDET; i++) {
                    if (alive[i] == 0) continue;
                    if (lane == 0) surv[ns] = (unsigned short)i;
                    ns++;
                    float4 bi = sbox[i];
                    float ai = sarea[i];
                    for (int j = i + 1 + lane; j < n2; j += 32) {
                        if (!alive[j]) continue;
                        float4 bj = sbox[j];
                        float ix1 = fmaxf(bi.x, bj.x), iy1 = fmaxf(bi.y, bj.y);
                        float ix2 = fminf(bi.z, bj.z), iy2 = fminf(bi.w, bj.w);
                        float inter = fmaxf(ix2 - ix1, 0.0f) * fmaxf(iy2 - iy1, 0.0f);
                        if (inter > 0.5f * (ai + sarea[j] - inter)) alive[j] = 0;
                    }
                    __syncwarp();
                }
                if (lane == 0) {
                    nsurv_s = ns;
                    sbase_s = atomicAdd(&g_svcnt[b], ns);
                }
            }
        }
        __syncthreads();

        const int so = b * SV_PER_IMG + sbase_s;
        for (int s = tid; s < nsurv_s; s += 256) {
            int i = surv[s];
            g_svbox[so + s] = sbox[i];
            g_svsc[so + s]  = __uint_as_float((unsigned)(ssort[i] >> 32));
            g_svlab[so + s] = (unsigned char)c;
        }
        }  // n2 > 0
    } else {
        // ---- global argmax fallback (n > 512; essentially never) ----
        const float Hf = load_dim(ph);
        const float Wf = load_dim(pw);
        const float off = fmaxf(Hf, Wf) + 1.0f;
        const float t = (float)c * off;
        for (int it = 0; it < NDET; it++) {
            float bv = -2e9f; int bi = 0;
            for (int j = tid; j < n; j += 256) {
                float v = g_cs[base + j];
                if (v > bv) { bv = v; bi = j; }
            }
            #pragma unroll
            for (int o = 16; o; o >>= 1) {
                float ov = __shfl_xor_sync(FULLM, bv, o);
                int   oi = __shfl_xor_sync(FULLM, bi, o);
                if (ov > bv || (ov == bv && oi < bi)) { bv = ov; bi = oi; }
            }
            if (lane == 0) { red_v[wid] = bv; red_i[wid] = bi; }
            __syncthreads();
            if (tid == 0) {
                for (int wv = 1; wv < 8; wv++)
                    if (red_v[wv] > red_v[0] ||
                        (red_v[wv] == red_v[0] && red_i[wv] < red_i[0])) {
                        red_v[0] = red_v[wv]; red_i[0] = red_i[wv];
                    }
                if (red_v[0] < -5e8f) stop_s = 1;
                else {
                    stop_s = 0; seli_s = red_i[0];
                    selbox_s = g_cbox[base + red_i[0]];
                    gsc_s = red_v[0];
                }
            }
            __syncthreads();
            if (stop_s) break;
            float4 bx = selbox_s;
            float ox1 = bx.x + t, oy1 = bx.y + t, ox2 = bx.z + t, oy2 = bx.w + t;
            float ai = (ox2 - ox1) * (oy2 - oy1);
            for (int j = tid; j < n; j += 256) {
                float v = g_cs[base + j];
                if (v < -5e8f) continue;
                float4 bj = g_cbox[base + j];
                float jx1 = bj.x + t, jy1 = bj.y + t, jx2 = bj.z + t, jy2 = bj.w + t;
                float ix1 = fmaxf(ox1, jx1), iy1 = fmaxf(oy1, jy1);
                float ix2 = fminf(ox2, jx2), iy2 = fminf(oy2, jy2);
                float inter = fmaxf(ix2 - ix1, 0.0f) * fmaxf(iy2 - iy1, 0.0f);
                float aj = (jx2 - jx1) * (jy2 - jy1);
                if (inter > 0.5f * (ai + aj - inter)) g_cs[base + j] = NEGV;
            }
            __syncthreads();
            if (tid == 0) {
                g_cs[base + seli_s] = NEGV;
                int slot = atomicAdd(&g_svcnt[b], 1);
                g_svbox[b * SV_PER_IMG + slot] = selbox_s;
                g_svsc[b * SV_PER_IMG + slot]  = gsc_s;
                g_svlab[b * SV_PER_IMG + slot] = (unsigned char)c;
            }
            __syncthreads();
        }
    }
    __syncthreads();
    if (tid == 0) g_ccnt[bc] = 0;   // self-reset for next graph replay
}

// ---------------------------------------------------------------------------
// Phase C: one block per image, 256 threads. Post-prune, nv ~ 100-300:
// direct rank sort over all survivors (no histogram machinery), emit top-100.
// ---------------------------------------------------------------------------
__global__ void __launch_bounds__(256)
topk_kernel(float* __restrict__ out) {
    const int b   = blockIdx.x;
    const int tid = threadIdx.x;
    const int wid = tid >> 5;
    const int lane = tid & 31;
    const int nv  = g_svcnt[b];
    const int base = b * SV_PER_IMG;
    const int nsel = (nv < NDET) ? nv : NDET;

    __shared__ unsigned long long keys[GCAP];
    __shared__ unsigned long long skeys[GCAP];

    if (nv <= GCAP) {
        for (int j = tid; j < nv; j += 256)
            keys[j] = ((unsigned long long)__float_as_uint(g_svsc[base + j]) << 32)
                    | (unsigned)(~j);
        __syncthreads();
        // rank sort descending (keys unique via embedded index)
        for (int i = tid; i < nv; i += 256) {
            unsigned long long ki = keys[i];
            int r = 0;
            for (int j = 0; j < nv; j++) r += (keys[j] > ki);
            if (r < GCAP) skeys[r] = ki;
        }
        __syncthreads();
    } else {
        // destructive argmax fallback (nv > 1024; essentially never)
        __shared__ float red_v[8];
        __shared__ int   red_i[8];
        for (int it = 0; it < nsel; it++) {
            float bv = -2e9f; int bi = 0;
            for (int j = tid; j < nv; j += 256) {
                float v = g_svsc[base + j];
                if (v > bv) { bv = v; bi = j; }
            }
            #pragma unroll
            for (int o = 16; o; o >>= 1) {
                float ov = __shfl_xor_sync(FULLM, bv, o);
                int   oi = __shfl_xor_sync(FULLM, bi, o);
                if (ov > bv || (ov == bv && oi < bi)) { bv = ov; bi = oi; }
            }
            if (lane == 0) { red_v[wid] = bv; red_i[wid] = bi; }
            __syncthreads();
            if (tid == 0) {
                for (int wv = 1; wv < 8; wv++)
                    if (red_v[wv] > red_v[0] ||
                        (red_v[wv] == red_v[0] && red_i[wv] < red_i[0])) {
                        red_v[0] = red_v[wv]; red_i[0] = red_i[wv];
                    }
                int bsel = red_i[0];
                skeys[it] = ((unsigned long long)__float_as_uint(red_v[0]) << 32)
                          | (unsigned)(~bsel);
                g_svsc[base + bsel] = NEGV;
            }
            __syncthreads();
        }
    }

    // emit: [boxes 8*100*4][scores 8*100][labels 8*100][keep 8*100]
    const int SC0 = B_IMG * NDET * 4;
    const int LB0 = SC0 + B_IMG * NDET;
    const int KP0 = LB0 + B_IMG * NDET;
    for (int i = tid; i < NDET; i += 256) {
        float4 bx = make_float4(0.f, 0.f, 0.f, 0.f);
        float sc = 0.0f, lb = 0.0f, kp = 0.0f;
        if (i < nsel) {
            unsigned long long kk = skeys[i];
            int j = (int)(~(unsigned)kk);
            bx = g_svbox[base + j];
            sc = __uint_as_float((unsigned)(kk >> 32));
            lb = (float)g_svlab[base + j];
            kp = 1.0f;
        }
        float* ob = out + ((size_t)b * NDET + i) * 4;
        ob[0] = bx.x; ob[1] = bx.y; ob[2] = bx.z; ob[3] = bx.w;
        out[SC0 + b * NDET + i] = sc;
        out[LB0 + b * NDET + i] = lb;
        out[KP0 + b * NDET + i] = kp;
    }
    __syncthreads();
    if (tid == 0) g_svcnt[b] = 0;   // self-reset for next graph replay
}

extern "C" void kernel_launch(void* const* d_in, const int* in_sizes, int n_in,
                              void* d_out, int out_size) {
    const float* logits = (const float*)d_in[0];
    const float* reg    = (const float*)d_in[1];
    const float* props  = (const float*)d_in[2];
    const int*   ih     = (const int*)d_in[3];
    const int*   iw     = (const int*)d_in[4];
    float* out = (float*)d_out;

    phaseAB_kernel<<<NBLKA, 256>>>(logits, reg, props, ih, iw);
    thresh_kernel<<<B_IMG, 1024>>>();
    class_nms_kernel<<<dim3(NCM1, B_IMG), 256>>>(ih, iw);
    topk_kernel<<<B_IMG, 256>>>(out);
}

// round 17
// speedup vs baseline: 1.3082x; 1.3082x over previous
#include <cuda_runtime.h>
#include <cstdint>
#include <math.h>

#define B_IMG 8
#define NPROP 4000
#define NCLS 91
#define NCM1 90
#define CAPC 4000                    // worst-case candidates per (image,class)
#define NDET 100
#define NEGV -1e9f
#define CAPSM 512                    // smem sort cap for class NMS
#define MASKN 320                    // mask-path cap
#define MW 10                        // u32 mask words per row (MASKN/32)
#define SV_PER_IMG (NCM1 * NDET)     // 9000 survivors per image (capped)
#define GCAP 1024                    // topk gather capacity
#define HB 256                       // histogram bins (key>>18)
#define HLO8 3840                    // (key>>18) offset
#define NBLKA 2000                   // phaseAB blocks (16 proposals each)
#define QCAP 320                     // smem queue cap (<=20 passers/proposal)
#define FULLM 0xffffffffu

static __device__ float4        g_cbox[B_IMG * NCM1 * CAPC];
static __device__ float         g_cs[B_IMG * NCM1 * CAPC];
static __device__ int           g_ccnt[B_IMG * NCM1];    // zero-init, self-reset
static __device__ float4        g_svbox[B_IMG * SV_PER_IMG];
static __device__ float         g_svsc[B_IMG * SV_PER_IMG];
static __device__ unsigned char g_svlab[B_IMG * SV_PER_IMG];
static __device__ int           g_svcnt[B_IMG];          // zero-init, self-reset
static __device__ int           g_hist[B_IMG * HB];      // zero-init, topk re-zeros
static __device__ float         g_T[B_IMG];              // overwritten each replay

__device__ __forceinline__ float load_dim(const int* p) {
    int vi = *p;
    if (vi > 0 && vi < 1000000) return (float)vi;
    return __int_as_float(vi);
}

__device__ __forceinline__ int score_bkt(unsigned keybits) {
    int bkt = (int)(keybits >> 18) - HLO8;
    return max(0, min(HB - 1, bkt));
}

// ---------------------------------------------------------------------------
// Phase AB (fused): softmax + threshold filter -> smem queue -> dense decode.
// (at MUFU floor ~20us; unchanged from R15)
// ---------------------------------------------------------------------------
__global__ void __launch_bounds__(256)
phaseAB_kernel(const float* __restrict__ logits,
               const float* __restrict__ reg,
               const float* __restrict__ props,
               const int* __restrict__ ph,
               const int* __restrict__ pw) {
    const int warp = threadIdx.x >> 5;
    const int lane = threadIdx.x & 31;
    const int p0 = (blockIdx.x * 8 + warp) << 1;

    __shared__ unsigned long long q[QCAP];
    __shared__ int s_cnt;
    if (threadIdx.x == 0) s_cnt = 0;
    __syncthreads();

    const float* z0 = logits + (size_t)p0 * NCLS;
    const float* z1 = z0 + NCLS;

    float e[2][3];
    e[0][0] = __expf(z0[lane]);
    e[1][0] = __expf(z1[lane]);
    e[0][1] = __expf(z0[lane + 32]);
    e[1][1] = __expf(z1[lane + 32]);
    e[0][2] = (lane < NCLS - 64) ? __expf(z0[lane + 64]) : 0.0f;
    e[1][2] = (lane < NCLS - 64) ? __expf(z1[lane + 64]) : 0.0f;

    float ssum[2];
    ssum[0] = e[0][0] + e[0][1] + e[0][2];
    ssum[1] = e[1][0] + e[1][1] + e[1][2];
    #pragma unroll
    for (int o = 16; o; o >>= 1) {
        ssum[0] += __shfl_xor_sync(FULLM, ssum[0], o);
        ssum[1] += __shfl_xor_sync(FULLM, ssum[1], o);
    }

    bool pass[6];
    int cnt = 0;
    #pragma unroll
    for (int k = 0; k < 2; k++) {
        float thr = 0.05f * ssum[k];
        #pragma unroll
        for (int t = 0; t < 3; t++) {
            int c = lane + 32 * t;
            bool pk = (c > 0) && (c < NCLS) && (e[k][t] > thr);
            pass[k * 3 + t] = pk;
            cnt += pk ? 1 : 0;
        }
    }

    int incl = cnt;
    #pragma unroll
    for (int o = 1; o < 32; o <<= 1) {
        int v = __shfl_up_sync(FULLM, incl, o);
        if (lane >= o) incl += v;
    }
    int total = __shfl_sync(FULLM, incl, 31);
    int wbase = 0;
    if (total > 0) {
        if (lane == 31) wbase = atomicAdd(&s_cnt, total);
        wbase = __shfl_sync(FULLM, wbase, 31);
        int off = wbase + incl - cnt;
        #pragma unroll
        for (int k = 0; k < 2; k++) {
            #pragma unroll
            for (int t = 0; t < 3; t++) {
                if (pass[k * 3 + t]) {
                    int c = lane + 32 * t;
                    float sc = e[k][t] / ssum[k];
                    unsigned idx = ((unsigned)(p0 + k) << 7) | (unsigned)c;
                    q[off++] = ((unsigned long long)__float_as_uint(sc) << 32) | idx;
                }
            }
        }
    }
    __syncthreads();

    const int qcnt = s_cnt;
    const float Wf = load_dim(pw);
    const float Hf = load_dim(ph);
    const float CLIPV = 4.135166556742356f;  // log(1000/16)

    for (int i = threadIdx.x; i < qcnt; i += 256) {
        unsigned long long en = q[i];
        float sc = __uint_as_float((unsigned)(en >> 32));
        unsigned idx = (unsigned)en;
        int p = idx >> 7, c = idx & 127;

        float4 pr = ((const float4*)props)[p];
        float w = pr.z - pr.x, h = pr.w - pr.y;
        float cx = pr.x + 0.5f * w, cy = pr.y + 0.5f * h;
        float4 r = ((const float4*)reg)[p * NCLS + c];

        float dx = r.x / 10.0f, dy = r.y / 10.0f;
        float dw = fminf(r.z / 5.0f, CLIPV);
        float dh = fminf(r.w / 5.0f, CLIPV);
        float pcx = dx * w + cx, pcy = dy * h + cy;
        float pwd = __expf(dw) * w, phd = __expf(dh) * h;
        float x1 = pcx - 0.5f * pwd, y1 = pcy - 0.5f * phd;
        float x2 = pcx + 0.5f * pwd, y2 = pcy + 0.5f * phd;
        x1 = fminf(fmaxf(x1, 0.0f), Wf); x2 = fminf(fmaxf(x2, 0.0f), Wf);
        y1 = fminf(fmaxf(y1, 0.0f), Hf); y2 = fminf(fmaxf(y2, 0.0f), Hf);
        if ((x2 - x1) >= 0.01f && (y2 - y1) >= 0.01f) {
            int b = p / NPROP;
            int bc = b * NCM1 + (c - 1);
            int pos = atomicAdd(&g_ccnt[bc], 1);
            size_t o = (size_t)bc * CAPC + pos;
            g_cbox[o] = make_float4(x1, y1, x2, y2);
            g_cs[o]   = sc;
        }
    }
}

// ---------------------------------------------------------------------------
// Threshold kernel: one block per image. Per class: top survivor score and
// best non-overlapping (2nd survivor) score — both provably greedy survivors.
// T = 100th largest of these; candidates with score < T are provably
// irrelevant to the final output. (unchanged from R15)
// ---------------------------------------------------------------------------
__global__ void __launch_bounds__(1024)
thresh_kernel(void) {
    const int b = blockIdx.x;
    const int tid = threadIdx.x;
    const int wid = tid >> 5;
    const int lane = tid & 31;

    __shared__ unsigned long long vals[192];
    __shared__ float T_s;
    for (int i = tid; i < 192; i += 1024) vals[i] = 0ull;
    if (tid == 0) T_s = 0.0f;
    __syncthreads();

    for (int t = wid; t < NCM1; t += 32) {
        const int bc = b * NCM1 + t;
        const int n = g_ccnt[bc];
        if (n == 0) continue;               // n uniform across warp
        const size_t base = (size_t)bc * CAPC;

        float m1 = -2e9f; int i1 = 0x7fffffff;
        for (int j = lane; j < n; j += 32) {
            float s = g_cs[base + j];
            if (s > m1) { m1 = s; i1 = j; }
        }
        #pragma unroll
        for (int o = 16; o; o >>= 1) {
            float ov = __shfl_xor_sync(FULLM, m1, o);
            int   oi = __shfl_xor_sync(FULLM, i1, o);
            if (ov > m1 || (ov == m1 && oi < i1)) { m1 = ov; i1 = oi; }
        }

        float4 b1 = g_cbox[base + i1];
        float a1 = (b1.z - b1.x) * (b1.w - b1.y);
        float m2 = -2e9f;
        for (int j = lane; j < n; j += 32) {
            if (j == i1) continue;
            float s = g_cs[base + j];
            if (s <= m2) continue;
            float4 bj = g_cbox[base + j];
            float ix1 = fmaxf(b1.x, bj.x), iy1 = fmaxf(b1.y, bj.y);
            float ix2 = fminf(b1.z, bj.z), iy2 = fminf(b1.w, bj.w);
            float inter = fmaxf(ix2 - ix1, 0.0f) * fmaxf(iy2 - iy1, 0.0f);
            float aj = (bj.z - bj.x) * (bj.w - bj.y);
            if (!(inter > 0.5f * (a1 + aj - inter))) m2 = s;   // survives round 1
        }
        #pragma unroll
        for (int o = 16; o; o >>= 1)
            m2 = fmaxf(m2, __shfl_xor_sync(FULLM, m2, o));

        if (lane == 0) {
            vals[2 * t] = ((unsigned long long)__float_as_uint(m1) << 32)
                        | (unsigned)(2 * t);
            if (m2 > 0.0f)
                vals[2 * t + 1] = ((unsigned long long)__float_as_uint(m2) << 32)
                                | (unsigned)(2 * t + 1);
        }
    }
    __syncthreads();

    if (tid < 192) {
        unsigned long long ki = vals[tid];
        if (ki != 0ull) {
            int r = 0;
            for (int j = 0; j < 192; j++) r += (vals[j] > ki);
            if (r == 99) T_s = __uint_as_float((unsigned)(ki >> 32));
        }
    }
    __syncthreads();
    if (tid == 0) g_T[b] = T_s;
}

// ---------------------------------------------------------------------------
// Phase B: one block per (image,class). Prune to score >= T[b] (exact), then
// x4-row ballot rank sort + x4-row ballot mask build + warp-0 register greedy
// scan. Survivors + 256-bin per-image histogram to global. (R15 + new bins)
// ---------------------------------------------------------------------------
__global__ void __launch_bounds__(256, 5)
class_nms_kernel(const int* __restrict__ ph, const int* __restrict__ pw) {
    const int c  = blockIdx.x + 1;
    const int b  = blockIdx.y;
    const int bc = b * NCM1 + (c - 1);
    const int tid = threadIdx.x;
    const int wid = tid >> 5;
    const int lane = tid & 31;
    const int n = g_ccnt[bc];
    if (n == 0) return;

    __shared__ unsigned long long skey[CAPSM];
    __shared__ unsigned long long ssort[CAPSM];
    __shared__ float4             sbox[CAPSM];
    __shared__ float              sarea[CAPSM];
    __shared__ unsigned int       mrow[MASKN * MW];
    __shared__ unsigned char      alive[CAPSM];
    __shared__ unsigned short     surv[NDET];
    __shared__ int                nsurv_s, sbase_s, cn_s;
    __shared__ float              red_v[8];
    __shared__ int                red_i[8];
    __shared__ int                stop_s, seli_s;
    __shared__ float4             selbox_s;
    __shared__ float              gsc_s;

    const size_t base = (size_t)bc * CAPC;

    if (n <= CAPSM) {
        // ---- prune + compact (score >= T is exact; see thresh_kernel) ----
        const float T = g_T[b];
        if (tid == 0) cn_s = 0;
        __syncthreads();
        for (int j = tid; j < n; j += 256) {
            float s = g_cs[base + j];
            if (s >= T) {
                int p = atomicAdd(&cn_s, 1);
                skey[p] = ((unsigned long long)__float_as_uint(s) << 32)
                        | (unsigned)j;
            }
        }
        __syncthreads();
        const int n2 = cn_s;

        if (n2 > 0) {
        const int NW32 = (n2 + 31) >> 5;
        const int im = n2 - 1;

        // x4-row ballot rank sort
        for (int i0 = wid << 2; i0 < n2; i0 += 32) {
            unsigned long long k0 = skey[i0];
            unsigned long long k1 = skey[min(i0 + 1, im)];
            unsigned long long k2 = skey[min(i0 + 2, im)];
            unsigned long long k3 = skey[min(i0 + 3, im)];
            int r0 = 0, r1 = 0, r2 = 0, r3 = 0;
            for (int jb = 0; jb < NW32; jb++) {
                int j = (jb << 5) + lane;
                bool v = j < n2;
                unsigned long long kj = skey[v ? j : 0];
                r0 += __popc(__ballot_sync(FULLM, v && (kj > k0)));
                r1 += __popc(__ballot_sync(FULLM, v && (kj > k1)));
                r2 += __popc(__ballot_sync(FULLM, v && (kj > k2)));
                r3 += __popc(__ballot_sync(FULLM, v && (kj > k3)));
            }
            if (lane < 4 && i0 + lane < n2) {
                int rr = (lane == 0) ? r0 : (lane == 1) ? r1 : (lane == 2) ? r2 : r3;
                unsigned long long kk =
                    (lane == 0) ? k0 : (lane == 1) ? k1 : (lane == 2) ? k2 : k3;
                ssort[rr] = kk;
            }
        }
        __syncthreads();

        for (int i = tid; i < n2; i += 256) {
            float4 bx = g_cbox[base + (unsigned)(ssort[i] & 0xffffffffu)];
            sbox[i]  = bx;
            sarea[i] = (bx.z - bx.x) * (bx.w - bx.y);
        }
        __syncthreads();

        if (n2 <= MASKN) {
            // ---- x4-row ballot mask build ----
            for (int i0 = wid << 2; i0 < n2; i0 += 32) {
                float4 b0 = sbox[i0];
                float4 b1 = sbox[min(i0 + 1, im)];
                float4 b2 = sbox[min(i0 + 2, im)];
                float4 b3 = sbox[min(i0 + 3, im)];
                float a0 = sarea[i0];
                float a1 = sarea[min(i0 + 1, im)];
                float a2 = sarea[min(i0 + 2, im)];
                float a3 = sarea[min(i0 + 3, im)];
                for (int jb = i0 >> 5; jb < NW32; jb++) {
                    int j = (jb << 5) + lane;
                    bool v = j < n2;
                    float4 bj = sbox[v ? j : 0];
                    float aj  = sarea[v ? j : 0];
                    int jgt = j - i0;
                    float ix1, iy1, ix2, iy2, inter;
                    ix1 = fmaxf(b0.x, bj.x); iy1 = fmaxf(b0.y, bj.y);
                    ix2 = fminf(b0.z, bj.z); iy2 = fminf(b0.w, bj.w);
                    inter = fmaxf(ix2 - ix1, 0.0f) * fmaxf(iy2 - iy1, 0.0f);
                    unsigned m0 = __ballot_sync(FULLM,
                        v && (jgt > 0) && (inter > 0.5f * (a0 + aj - inter)));
                    ix1 = fmaxf(b1.x, bj.x); iy1 = fmaxf(b1.y, bj.y);
                    ix2 = fminf(b1.z, bj.z); iy2 = fminf(b1.w, bj.w);
                    inter = fmaxf(ix2 - ix1, 0.0f) * fmaxf(iy2 - iy1, 0.0f);
                    unsigned m1 = __ballot_sync(FULLM,
                        v && (jgt > 1) && (inter > 0.5f * (a1 + aj - inter)));
                    ix1 = fmaxf(b2.x, bj.x); iy1 = fmaxf(b2.y, bj.y);
                    ix2 = fminf(b2.z, bj.z); iy2 = fminf(b2.w, bj.w);
                    inter = fmaxf(ix2 - ix1, 0.0f) * fmaxf(iy2 - iy1, 0.0f);
                    unsigned m2 = __ballot_sync(FULLM,
                        v && (jgt > 2) && (inter > 0.5f * (a2 + aj - inter)));
                    ix1 = fmaxf(b3.x, bj.x); iy1 = fmaxf(b3.y, bj.y);
                    ix2 = fminf(b3.z, bj.z); iy2 = fminf(b3.w, bj.w);
                    inter = fmaxf(ix2 - ix1, 0.0f) * fmaxf(iy2 - iy1, 0.0f);
                    unsigned m3 = __ballot_sync(FULLM,
                        v && (jgt > 3) && (inter > 0.5f * (a3 + aj - inter)));
                    if (lane < 4 && i0 + lane < n2) {
                        unsigned mv =
                            (lane == 0) ? m0 : (lane == 1) ? m1 : (lane == 2) ? m2 : m3;
                        mrow[(i0 + lane) * MW + jb] = mv;
                    }
                }
            }
            __syncthreads();

            // ---- greedy scan, warp 0, dead-words in registers ----
            if (wid == 0) {
                unsigned dead = 0;    // lane L owns dead word L
                int ns = 0;
                for (int i = 0; i < n2 && ns < NDET; i++) {
                    unsigned dw = __shfl_sync(FULLM, dead, i >> 5);
                    if (!((dw >> (i & 31)) & 1u)) {
                        if (lane == 0) surv[ns] = (unsigned short)i;
                        ns++;
                        if (lane < NW32 && lane >= (i >> 5))
                            dead |= mrow[i * MW + lane];
                    }
                }
                if (lane == 0) {
                    nsurv_s = ns;
                    sbase_s = atomicAdd(&g_svcnt[b], ns);
                }
            }
        } else {
            // ---- maskless warp-greedy mid path (MASKN < n2 <= CAPSM) ----
            for (int i = tid; i < n2; i += 256) alive[i] = 1;
            __syncthreads();
            if (wid == 0) {
                int ns = 0;
                for (int i = 0; i < n2 && ns < NDET; i++) {
                    if (alive[i] == 0) continue;
                    if (lane == 0) surv[ns] = (unsigned short)i;
                    ns++;
                    float4 bi = sbox[i];
                    float ai = sarea[i];
                    for (int j = i + 1 + lane; j < n2; j += 32) {
                        if (!alive[j]) continue;
                        float4 bj = sbox[j];
                        float ix1 = fmaxf(bi.x, bj.x), iy1 = fmaxf(bi.y, bj.y);
                        float ix2 = fminf(bi.z, bj.z), iy2 = fminf(bi.w, bj.w);
                        float inter = fmaxf(ix2 - ix1, 0.0f) * fmaxf(iy2 - iy1, 0.0f);
                        if (inter > 0.5f * (ai + sarea[j] - inter)) alive[j] = 0;
                    }
                    __syncwarp();
                }
                if (lane == 0) {
                    nsurv_s = ns;
                    sbase_s = atomicAdd(&g_svcnt[b], ns);
                }
            }
        }
        __syncthreads();

        const int so = b * SV_PER_IMG + sbase_s;
        for (int s = tid; s < nsurv_s; s += 256) {
            int i = surv[s];
            unsigned kb = (unsigned)(ssort[i] >> 32);
            g_svbox[so + s] = sbox[i];
            g_svsc[so + s]  = __uint_as_float(kb);
            g_svlab[so + s] = (unsigned char)c;
            atomicAdd(&g_hist[b * HB + score_bkt(kb)], 1);
        }
        }  // n2 > 0
    } else {
        // ---- global argmax fallback (n > 512; essentially never) ----
        const float Hf = load_dim(ph);
        const float Wf = load_dim(pw);
        const float off = fmaxf(Hf, Wf) + 1.0f;
        const float t = (float)c * off;
        for (int it = 0; it < NDET; it++) {
            float bv = -2e9f; int bi = 0;
            for (int j = tid; j < n; j += 256) {
                float v = g_cs[base + j];
                if (v > bv) { bv = v; bi = j; }
            }
            #pragma unroll
            for (int o = 16; o; o >>= 1) {
                float ov = __shfl_xor_sync(FULLM, bv, o);
                int   oi = __shfl_xor_sync(FULLM, bi, o);
                if (ov > bv || (ov == bv && oi < bi)) { bv = ov; bi = oi; }
            }
            if (lane == 0) { red_v[wid] = bv; red_i[wid] = bi; }
            __syncthreads();
            if (tid == 0) {
                for (int wv = 1; wv < 8; wv++)
                    if (red_v[wv] > red_v[0] ||
                        (red_v[wv] == red_v[0] && red_i[wv] < red_i[0])) {
                        red_v[0] = red_v[wv]; red_i[0] = red_i[wv];
                    }
                if (red_v[0] < -5e8f) stop_s = 1;
                else {
                    stop_s = 0; seli_s = red_i[0];
                    selbox_s = g_cbox[base + red_i[0]];
                    gsc_s = red_v[0];
                }
            }
            __syncthreads();
            if (stop_s) break;
            float4 bx = selbox_s;
            float ox1 = bx.x + t, oy1 = bx.y + t, ox2 = bx.z + t, oy2 = bx.w + t;
            float ai = (ox2 - ox1) * (oy2 - oy1);
            for (int j = tid; j < n; j += 256) {
                float v = g_cs[base + j];
                if (v < -5e8f) continue;
                float4 bj = g_cbox[base + j];
                float jx1 = bj.x + t, jy1 = bj.y + t, jx2 = bj.z + t, jy2 = bj.w + t;
                float ix1 = fmaxf(ox1, jx1), iy1 = fmaxf(oy1, jy1);
                float ix2 = fminf(ox2, jx2), iy2 = fminf(oy2, jy2);
                float inter = fmaxf(ix2 - ix1, 0.0f) * fmaxf(iy2 - iy1, 0.0f);
                float aj = (jx2 - jx1) * (jy2 - jy1);
                if (inter > 0.5f * (ai + aj - inter)) g_cs[base + j] = NEGV;
            }
            __syncthreads();
            if (tid == 0) {
                g_cs[base + seli_s] = NEGV;
                int slot = atomicAdd(&g_svcnt[b], 1);
                g_svbox[b * SV_PER_IMG + slot] = selbox_s;
                g_svsc[b * SV_PER_IMG + slot]  = gsc_s;
                g_svlab[b * SV_PER_IMG + slot] = (unsigned char)c;
                atomicAdd(&g_hist[b * HB + score_bkt(__float_as_uint(gsc_s))], 1);
            }
            __syncthreads();
        }
    }
    __syncthreads();
    if (tid == 0) g_ccnt[bc] = 0;   // self-reset for next graph replay
}

// ---------------------------------------------------------------------------
// Phase C: one block per image, 256 threads. 256-bin precomputed histogram
// -> 2-level suffix sum -> pivot -> gather -> rank sort -> emit.
// ---------------------------------------------------------------------------
__global__ void __launch_bounds__(256)
topk_kernel(float* __restrict__ out) {
    const int b   = blockIdx.x;
    const int tid = threadIdx.x;
    const int wid = tid >> 5;
    const int lane = tid & 31;
    const int n   = g_svcnt[b];
    const int base = b * SV_PER_IMG;
    const int nsel = (n < NDET) ? n : NDET;

    __shared__ int hist[HB];
    __shared__ int warpsum[8];
    __shared__ int warp_above[8];
    __shared__ unsigned long long keys[GCAP];
    __shared__ unsigned long long skeys[GCAP];
    __shared__ int gcnt_s, pb_s;

    // load precomputed histogram; re-zero global copy for next replay
    {
        hist[tid] = g_hist[b * HB + tid];
        g_hist[b * HB + tid] = 0;
    }
    if (tid == 0) { gcnt_s = 0; pb_s = 0; }
    __syncthreads();

    // 2-level inclusive suffix sum over 256 bins (8 warps x 32 bins)
    {
        int h = hist[tid];
        int acc = h;
        #pragma unroll
        for (int o = 1; o < 32; o <<= 1) {
            int v = __shfl_down_sync(FULLM, acc, o);
            if (lane + o < 32) acc += v;          // acc = sum of lanes >= lane
        }
        if (lane == 0) warpsum[wid] = acc;        // total of this warp's bins
        __syncthreads();
        if (wid == 0 && lane < 8) {
            int cs = warpsum[lane];
            int a2 = cs;
            #pragma unroll
            for (int o = 1; o < 8; o <<= 1) {
                int v = __shfl_down_sync(0xffu, a2, o);
                if (lane + o < 8) a2 += v;        // sum of warps >= lane
            }
            warp_above[lane] = a2 - cs;           // warps strictly above
        }
        __syncthreads();
        hist[tid] = acc + warp_above[wid];        // inclusive suffix at bin tid
    }
    __syncthreads();

    // pivot bucket: largest i with suffix >= nsel
    if (nsel > 0) {
        int s = hist[tid];
        int sn = (tid + 1 < HB) ? hist[tid + 1] : 0;
        if (s >= nsel && sn < nsel) pb_s = tid;
    }
    __syncthreads();
    const int pb = pb_s;
    const int m  = (nsel > 0) ? hist[pb] : 0;

    if (m <= GCAP) {
        for (int j = tid; j < n; j += 256) {
            unsigned k = __float_as_uint(g_svsc[base + j]);
            if (score_bkt(k) >= pb) {
                int slot = atomicAdd(&gcnt_s, 1);
                keys[slot] = ((unsigned long long)k << 32) | (unsigned)(~j);
            }
        }
        __syncthreads();
        // rank sort descending (keys unique via embedded index)
        for (int i = tid; i < m; i += 256) {
            unsigned long long ki = keys[i];
            int r = 0;
            for (int j = 0; j < m; j++) r += (keys[j] > ki);
            skeys[r] = ki;
        }
        __syncthreads();
    } else {
        // destructive argmax fallback (pathological pile-up only)
        __shared__ float red_v[8];
        __shared__ int   red_i[8];
        for (int it = 0; it < nsel; it++) {
            float bv = -2e9f; int bi = 0;
            for (int j = tid; j < n; j += 256) {
                float v = g_svsc[base + j];
                if (v > bv) { bv = v; bi = j; }
            }
            #pragma unroll
            for (int o = 16; o; o >>= 1) {
                float ov = __shfl_xor_sync(FULLM, bv, o);
                int   oi = __shfl_xor_sync(FULLM, bi, o);
                if (ov > bv || (ov == bv && oi < bi)) { bv = ov; bi = oi; }
            }
            if (lane == 0) { red_v[wid] = bv; red_i[wid] = bi; }
            __syncthreads();
            if (tid == 0) {
                for (int wv = 1; wv < 8; wv++)
                    if (red_v[wv] > red_v[0] ||
                        (red_v[wv] == red_v[0] && red_i[wv] < red_i[0])) {
                        red_v[0] = red_v[wv]; red_i[0] = red_i[wv];
                    }
                int bsel = red_i[0];
                skeys[it] = ((unsigned long long)__float_as_uint(red_v[0]) << 32)
                          | (unsigned)(~bsel);
                g_svsc[base + bsel] = NEGV;
            }
            __syncthreads();
        }
    }

    // emit: [boxes 8*100*4][scores 8*100][labels 8*100][keep 8*100]
    const int SC0 = B_IMG * NDET * 4;
    const int LB0 = SC0 + B_IMG * NDET;
    const int KP0 = LB0 + B_IMG * NDET;
    for (int i = tid; i < NDET; i += 256) {
        float4 bx = make_float4(0.f, 0.f, 0.f, 0.f);
        float sc = 0.0f, lb = 0.0f, kp = 0.0f;
        if (i < nsel) {
            unsigned long long kk = skeys[i];
            int j = (int)(~(unsigned)kk);
            bx = g_svbox[base + j];
            sc = __uint_as_float((unsigned)(kk >> 32));
            lb = (float)g_svlab[base + j];
            kp = 1.0f;
        }
        float* ob = out + ((size_t)b * NDET + i) * 4;
        ob[0] = bx.x; ob[1] = bx.y; ob[2] = bx.z; ob[3] = bx.w;
        out[SC0 + b * NDET + i] = sc;
        out[LB0 + b * NDET + i] = lb;
        out[KP0 + b * NDET + i] = kp;
    }
    __syncthreads();
    if (tid == 0) g_svcnt[b] = 0;   // self-reset for next graph replay
}

extern "C" void kernel_launch(void* const* d_in, const int* in_sizes, int n_in,
                              void* d_out, int out_size) {
    const float* logits = (const float*)d_in[0];
    const float* reg    = (const float*)d_in[1];
    const float* props  = (const float*)d_in[2];
    const int*   ih     = (const int*)d_in[3];
    const int*   iw     = (const int*)d_in[4];
    float* out = (float*)d_out;

    phaseAB_kernel<<<NBLKA, 256>>>(logits, reg, props, ih, iw);
    thresh_kernel<<<B_IMG, 1024>>>();
    class_nms_kernel<<<dim3(NCM1, B_IMG), 256>>>(ih, iw);
    topk_kernel<<<B_IMG, 256>>>(out);
}